// round 2
// baseline (speedup 1.0000x reference)
#include <cuda_runtime.h>
#include <math.h>

#define HW    16384
#define NMODE 512
#define PI2   6.28318530717958647692f

// ---- scratch (device globals; allocation-free kernel_launch) ----
__device__ float2 g_XF [2048 * NMODE];        // forward DFT modes (both stages)
__device__ float2 g_OF [3 * 2048 * NMODE];    // kqv spectral output
__device__ float  g_kqv[100663296];           // [3][512][4][16384]
__device__ float  g_S  [32768];               // [8][64][64] scores
__device__ float  g_att[33554432];            // [8][256][16384] attn/gelu
__device__ float2 g_EOF[2048 * NMODE];        // end spectral output

// ---------------- forward partial DFT: 128x128 plane -> 32x16 modes ----------
static const int SM_FWD = 128*129*4 + 128*16*8 + 256*4;   // 83456 B

__global__ void k_fwd_dft(const float* __restrict__ src, float2* __restrict__ dst) {
    extern __shared__ float sm[];
    float*  xs = sm;                               // [128][129]
    float2* T1 = (float2*)(sm + 128*129);          // [128][16]
    float*  ct = (float*)(T1 + 128*16);
    float*  st = ct + 128;
    const int tid = threadIdx.x;                   // 256
    const float* x = src + (size_t)blockIdx.x * HW;

    if (tid < 128) { float a = (float)tid * (PI2/128.f); ct[tid] = cosf(a); st[tid] = sinf(a); }
    for (int i = tid; i < HW; i += 256) xs[(i >> 7)*129 + (i & 127)] = x[i];
    __syncthreads();

    {   // phase 1: T1[h][m2] = sum_w x[h][w] e^{-2pi i m2 w/128}
        int h = tid >> 1, m2b = (tid & 1) * 8;
        float2 acc[8];
        #pragma unroll
        for (int j = 0; j < 8; j++) acc[j] = make_float2(0.f, 0.f);
        for (int w = 0; w < 128; w++) {
            float xv = xs[h*129 + w];
            #pragma unroll
            for (int j = 0; j < 8; j++) {
                int idx = ((m2b + j) * w) & 127;
                acc[j].x += xv * ct[idx];
                acc[j].y -= xv * st[idx];
            }
        }
        #pragma unroll
        for (int j = 0; j < 8; j++) T1[h*16 + m2b + j] = acc[j];
    }
    __syncthreads();

    // phase 2: fold h with row-mode twiddles (rows 0..15 and 112..127)
    #pragma unroll
    for (int rep = 0; rep < 2; rep++) {
        int om  = tid*2 + rep;
        int m1i = om >> 4, m2 = om & 15;
        int r   = (m1i < 16) ? m1i : (m1i + 96);
        float sx = 0.f, sy = 0.f;
        for (int h = 0; h < 128; h++) {
            int idx = (r * h) & 127;
            float c = ct[idx], s = st[idx];
            float2 t = T1[h*16 + m2];
            sx += t.x*c + t.y*s;
            sy += t.y*c - t.x*s;
        }
        dst[(size_t)blockIdx.x * NMODE + om] = make_float2(sx*(1.f/16384.f), sy*(1.f/16384.f));
    }
}

// ---------------- kqv spectral multiply ----------------
__global__ void k_spec_kqv(const float* __restrict__ w1r, const float* __restrict__ w1i,
                           const float* __restrict__ w2r, const float* __restrict__ w2i) {
    int s = blockIdx.x >> 9, n = blockIdx.x & 511;
    int m = threadIdx.x;                 // 512
    bool top = m < 256;
    int mm = top ? m : (m - 256);
    const float* wr = top ? w1r : w2r;
    const float* wi = top ? w1i : w2i;

    float2 xv[4];
    #pragma unroll
    for (int i = 0; i < 4; i++) xv[i] = g_XF[(size_t)(n*4 + i) * NMODE + m];

    #pragma unroll
    for (int o = 0; o < 4; o++) {
        float ax = 0.f, ay = 0.f;
        #pragma unroll
        for (int i = 0; i < 4; i++) {
            float a = wr[s*4096 + (i*4 + o)*256 + mm];
            float b = wi[s*4096 + (i*4 + o)*256 + mm];
            ax += xv[i].x*a - xv[i].y*b;
            ay += xv[i].x*b + xv[i].y*a;
        }
        g_OF[((size_t)(s*512 + n)*4 + o) * NMODE + m] = make_float2(ax, ay);
    }
}

// ---------------- kqv inverse partial DFT + pointwise skip -------------------
static const int SM_IDFTK = (2048 + 8192)*8 + 256*4 + 16*4;   // 83008 B

__global__ void k_idft_kqv(const float* __restrict__ x, const float* __restrict__ skip) {
    extern __shared__ float sm[];
    float2* OFs = (float2*)sm;                 // [4][32][16]
    float2* U   = OFs + 2048;                  // [4][128][16]
    float*  ct  = (float*)(U + 8192);
    float*  st  = ct + 128;
    float*  sk  = st + 128;                    // [4][4] (o,i)
    const int tid = threadIdx.x;               // 256
    const int s = blockIdx.x >> 9, n = blockIdx.x & 511;

    if (tid < 128) { float a = (float)tid * (PI2/128.f); ct[tid] = cosf(a); st[tid] = sinf(a); }
    if (tid < 16)  sk[tid] = skip[s*16 + tid];
    for (int i = tid; i < 2048; i += 256)
        OFs[i] = g_OF[((size_t)(s*512 + n)*4) * NMODE + i];
    __syncthreads();

    // phase 1: U[o][h][m2] = a(m2) * sum_{m1} OF[o][m1][m2] e^{+2pi i r h/128}
    for (int e = tid; e < 8192; e += 256) {
        int o = e >> 11, rem = e & 2047, h = rem >> 4, m2 = rem & 15;
        float ux = 0.f, uy = 0.f;
        #pragma unroll
        for (int m1i = 0; m1i < 32; m1i++) {
            int r = (m1i < 16) ? m1i : (m1i + 96);
            int idx = (r * h) & 127;
            float c = ct[idx], sn = st[idx];
            float2 X = OFs[o*512 + m1i*16 + m2];
            ux += X.x*c  - X.y*sn;
            uy += X.x*sn + X.y*c;
        }
        float a = (m2 == 0) ? 1.f : 2.f;
        U[e] = make_float2(ux*a, uy*a);
    }
    __syncthreads();

    // phase 2: expand over m2 (Re part) + skip; thread = (w, o-pair)
    int w = tid & 127, o0 = (tid >> 7) * 2;
    float cw[16], sw[16];
    #pragma unroll
    for (int m2 = 0; m2 < 16; m2++) { int idx = (m2*w) & 127; cw[m2] = ct[idx]; sw[m2] = st[idx]; }
    float s00 = sk[o0*4+0], s01 = sk[o0*4+1], s02 = sk[o0*4+2], s03 = sk[o0*4+3];
    float s10 = sk[o0*4+4], s11 = sk[o0*4+5], s12 = sk[o0*4+6], s13 = sk[o0*4+7];
    size_t outbase = ((size_t)(s*512 + n)*4 + o0) * HW;
    size_t xbase   = (size_t)n * 4 * HW;

    for (int h = 0; h < 128; h++) {
        const float4* U0 = (const float4*)(U + (o0 << 11) + (h << 4));
        const float4* U1 = (const float4*)(U + ((o0+1) << 11) + (h << 4));
        float v0 = 0.f, v1 = 0.f;
        #pragma unroll
        for (int q = 0; q < 8; q++) {
            float4 a4 = U0[q];
            v0 += a4.x*cw[2*q] - a4.y*sw[2*q] + a4.z*cw[2*q+1] - a4.w*sw[2*q+1];
            float4 b4 = U1[q];
            v1 += b4.x*cw[2*q] - b4.y*sw[2*q] + b4.z*cw[2*q+1] - b4.w*sw[2*q+1];
        }
        int p = (h << 7) + w;
        float x0 = x[xbase + p],        x1 = x[xbase + HW + p];
        float x2 = x[xbase + 2*HW + p], x3 = x[xbase + 3*HW + p];
        v0 += s00*x0 + s01*x1 + s02*x2 + s03*x3;
        v1 += s10*x0 + s11*x1 + s12*x2 + s13*x3;
        g_kqv[outbase + p]      = v0;
        g_kqv[outbase + HW + p] = v1;
    }
}

// ---------------- attention --------------------------------------------------
__global__ void k_zeroS() {
    int i = blockIdx.x*256 + threadIdx.x;
    if (i < 32768) g_S[i] = 0.f;
}

static const int SM_SCORES = 2*64*257*4;   // 131584 B

__global__ void k_scores() {
    extern __shared__ float sm[];
    float* qs = sm;             // [64][257]
    float* ks = sm + 64*257;
    const int b = blockIdx.y, ch = blockIdx.x, tid = threadIdx.x;
    size_t qoff = ((size_t)512 + (size_t)b*64) * 65536 + (size_t)ch*256;  // q = kqv[1]
    size_t koff = ((size_t)b*64) * 65536 + (size_t)ch*256;                // k = kqv[0]
    for (int i = tid; i < 16384; i += 256) {
        int t = i >> 8, j = i & 255;
        qs[t*257 + j] = g_kqv[qoff + (size_t)t*65536 + j];
        ks[t*257 + j] = g_kqv[koff + (size_t)t*65536 + j];
    }
    __syncthreads();
    int t = tid >> 2, s0 = (tid & 3) * 16;
    float acc[16];
    #pragma unroll
    for (int j = 0; j < 16; j++) acc[j] = 0.f;
    for (int kk = 0; kk < 256; kk++) {
        float qv = qs[t*257 + kk];
        #pragma unroll
        for (int j = 0; j < 16; j++) acc[j] += qv * ks[(s0 + j)*257 + kk];
    }
    #pragma unroll
    for (int j = 0; j < 16; j++)
        atomicAdd(&g_S[(b*64 + t)*64 + s0 + j], acc[j] * (1.f/65536.f));
}

__global__ void k_softmax() {
    int b = blockIdx.x, t = threadIdx.x;           // 8 x 64
    float* row = &g_S[(b*64 + t)*64];
    float mx = -1e30f;
    for (int s = 0; s < 64; s++) mx = fmaxf(mx, row[s]);
    float sum = 0.f;
    for (int s = 0; s < 64; s++) { float v = expf(row[s] - mx); row[s] = v; sum += v; }
    float inv = 1.f / sum;
    for (int s = 0; s < 64; s++) row[s] *= inv;
}

__global__ void k_attnv() {
    __shared__ float As[4096];
    const int b = blockIdx.y, tid = threadIdx.x;
    const int p = blockIdx.x * 256 + tid;          // global feature 0..65535
    for (int i = tid; i < 4096; i += 256) As[i] = g_S[b*4096 + i];
    __syncthreads();
    float acc[64];
    #pragma unroll
    for (int t = 0; t < 64; t++) acc[t] = 0.f;
    size_t vbase = ((size_t)1024 + (size_t)b*64) * 65536 + p;   // v = kqv[2]
    for (int s = 0; s < 64; s++) {
        float vv = g_kqv[vbase + (size_t)s*65536];
        #pragma unroll
        for (int t = 0; t < 64; t++) acc[t] += As[t*64 + s] * vv;
    }
    size_t obase = (size_t)b * 4194304 + p;        // g_att[b][t*4+d][pix] = base + t*65536
    #pragma unroll
    for (int t = 0; t < 64; t++) g_att[obase + (size_t)t*65536] = acc[t];
}

// ---------------- InstanceNorm2d + exact GELU (in place) --------------------
__global__ void k_inorm() {
    __shared__ float w1s[8], w2s[8];
    float* ptr = g_att + (size_t)blockIdx.x * HW;
    const int tid = threadIdx.x;
    float s1 = 0.f, s2 = 0.f;
    for (int i = tid; i < HW; i += 256) { float v = ptr[i]; s1 += v; s2 += v*v; }
    for (int off = 16; off; off >>= 1) {
        s1 += __shfl_down_sync(0xffffffffu, s1, off);
        s2 += __shfl_down_sync(0xffffffffu, s2, off);
    }
    if ((tid & 31) == 0) { w1s[tid >> 5] = s1; w2s[tid >> 5] = s2; }
    __syncthreads();
    if (tid == 0) {
        float a = 0.f, c = 0.f;
        for (int i = 0; i < 8; i++) { a += w1s[i]; c += w2s[i]; }
        w1s[0] = a * (1.f/HW); w2s[0] = c * (1.f/HW);
    }
    __syncthreads();
    float mu = w1s[0];
    float inv = rsqrtf(w2s[0] - mu*mu + 1e-5f);
    for (int i = tid; i < HW; i += 256) {
        float v = (ptr[i] - mu) * inv;
        ptr[i] = v * normcdff(v);
    }
}

// ---------------- end spectral multiply -------------------------------------
__global__ void k_spec_end(const float* __restrict__ w1r, const float* __restrict__ w1i,
                           const float* __restrict__ w2r, const float* __restrict__ w2i) {
    const int m = threadIdx.x;                 // 512
    const int o0 = blockIdx.x * 2;             // 128 blocks
    bool top = m < 256;
    int mm = top ? m : (m - 256);
    const float* wr = top ? w1r : w2r;
    const float* wi = top ? w1i : w2i;
    float2 a0[8], a1[8];
    #pragma unroll
    for (int b = 0; b < 8; b++) { a0[b] = make_float2(0.f,0.f); a1[b] = make_float2(0.f,0.f); }
    for (int i = 0; i < 256; i++) {
        float wr0 = wr[((size_t)i*256 + o0    )*256 + mm];
        float wi0 = wi[((size_t)i*256 + o0    )*256 + mm];
        float wr1 = wr[((size_t)i*256 + o0 + 1)*256 + mm];
        float wi1 = wi[((size_t)i*256 + o0 + 1)*256 + mm];
        #pragma unroll
        for (int b = 0; b < 8; b++) {
            float2 xv = g_XF[((size_t)(b*256 + i)) * NMODE + m];
            a0[b].x += xv.x*wr0 - xv.y*wi0;  a0[b].y += xv.x*wi0 + xv.y*wr0;
            a1[b].x += xv.x*wr1 - xv.y*wi1;  a1[b].y += xv.x*wi1 + xv.y*wr1;
        }
    }
    #pragma unroll
    for (int b = 0; b < 8; b++) {
        g_EOF[((size_t)(b*256 + o0    )) * NMODE + m] = a0[b];
        g_EOF[((size_t)(b*256 + o0 + 1)) * NMODE + m] = a1[b];
    }
}

// ---------------- end inverse partial DFT -> d_out --------------------------
__global__ void k_idft_end(float* __restrict__ out) {
    __shared__ float2 OFs[512];
    __shared__ float2 U[2048];
    __shared__ float ct[128], st[128];
    const int tid = threadIdx.x;               // 256
    const int plane = blockIdx.x;              // 2048
    if (tid < 128) { float a = (float)tid * (PI2/128.f); ct[tid] = cosf(a); st[tid] = sinf(a); }
    for (int i = tid; i < 512; i += 256) OFs[i] = g_EOF[(size_t)plane*512 + i];
    __syncthreads();
    for (int e = tid; e < 2048; e += 256) {
        int h = e >> 4, m2 = e & 15;
        float ux = 0.f, uy = 0.f;
        #pragma unroll
        for (int m1i = 0; m1i < 32; m1i++) {
            int r = (m1i < 16) ? m1i : (m1i + 96);
            int idx = (r * h) & 127;
            float c = ct[idx], sn = st[idx];
            float2 X = OFs[m1i*16 + m2];
            ux += X.x*c  - X.y*sn;
            uy += X.x*sn + X.y*c;
        }
        float a = (m2 == 0) ? 1.f : 2.f;
        U[e] = make_float2(ux*a, uy*a);
    }
    __syncthreads();
    int w = tid & 127, h0 = (tid >> 7) * 64;
    float cw[16], sw[16];
    #pragma unroll
    for (int m2 = 0; m2 < 16; m2++) { int idx = (m2*w) & 127; cw[m2] = ct[idx]; sw[m2] = st[idx]; }
    for (int h = h0; h < h0 + 64; h++) {
        const float4* Up = (const float4*)(U + (h << 4));
        float v = 0.f;
        #pragma unroll
        for (int q = 0; q < 8; q++) {
            float4 a4 = Up[q];
            v += a4.x*cw[2*q] - a4.y*sw[2*q] + a4.z*cw[2*q+1] - a4.w*sw[2*q+1];
        }
        out[(size_t)plane*HW + (h << 7) + w] = v;
    }
}

// ---------------- end pointwise skip GEMM (accumulates into d_out) ----------
__global__ void k_endskip(const float* __restrict__ skip, float* __restrict__ out) {
    __shared__ float Ss[32][65];
    __shared__ float Gs[32][128];
    const int b = blockIdx.z, o0 = blockIdx.y * 64, p0 = blockIdx.x * 128;
    const int tid = threadIdx.x;
    const int px = tid & 31, oy = tid >> 5;
    float acc[8][4];
    #pragma unroll
    for (int j = 0; j < 8; j++)
        #pragma unroll
        for (int jj = 0; jj < 4; jj++) acc[j][jj] = 0.f;

    for (int kc = 0; kc < 256; kc += 32) {
        for (int i = tid; i < 2048; i += 256) {
            int orow = i >> 5, ic = i & 31;
            Ss[ic][orow] = skip[(size_t)(o0 + orow)*256 + kc + ic];
        }
        for (int i = tid; i < 4096; i += 256) {
            int ir = i >> 7, c = i & 127;
            Gs[ir][c] = g_att[((size_t)b*256 + kc + ir) * HW + p0 + c];
        }
        __syncthreads();
        #pragma unroll 8
        for (int k = 0; k < 32; k++) {
            float gv[4], sv[8];
            #pragma unroll
            for (int jj = 0; jj < 4; jj++) gv[jj] = Gs[k][px + 32*jj];
            #pragma unroll
            for (int j = 0; j < 8; j++) sv[j] = Ss[k][oy + 8*j];
            #pragma unroll
            for (int j = 0; j < 8; j++)
                #pragma unroll
                for (int jj = 0; jj < 4; jj++) acc[j][jj] += sv[j] * gv[jj];
        }
        __syncthreads();
    }
    #pragma unroll
    for (int j = 0; j < 8; j++)
        #pragma unroll
        for (int jj = 0; jj < 4; jj++) {
            size_t oidx = ((size_t)b*256 + o0 + oy + 8*j) * HW + p0 + px + 32*jj;
            out[oidx] += acc[j][jj];
        }
}

// ---------------- launch -----------------------------------------------------
extern "C" void kernel_launch(void* const* d_in, const int* in_sizes, int n_in,
                              void* d_out, int out_size) {
    const float* x        = (const float*)d_in[0];
    const float* kqv_w1r  = (const float*)d_in[1];
    const float* kqv_w1i  = (const float*)d_in[2];
    const float* kqv_w2r  = (const float*)d_in[3];
    const float* kqv_w2i  = (const float*)d_in[4];
    const float* kqv_skip = (const float*)d_in[5];
    const float* end_w1r  = (const float*)d_in[6];
    const float* end_w1i  = (const float*)d_in[7];
    const float* end_w2r  = (const float*)d_in[8];
    const float* end_w2i  = (const float*)d_in[9];
    const float* end_skip = (const float*)d_in[10];
    float* out = (float*)d_out;

    cudaFuncSetAttribute(k_fwd_dft,  cudaFuncAttributeMaxDynamicSharedMemorySize, SM_FWD);
    cudaFuncSetAttribute(k_idft_kqv, cudaFuncAttributeMaxDynamicSharedMemorySize, SM_IDFTK);
    cudaFuncSetAttribute(k_scores,   cudaFuncAttributeMaxDynamicSharedMemorySize, SM_SCORES);

    float2* gXF;  cudaGetSymbolAddress((void**)&gXF,  g_XF);
    float*  gAtt; cudaGetSymbolAddress((void**)&gAtt, g_att);

    // stage 1: per-(token,channel) partial DFT
    k_fwd_dft<<<2048, 256, SM_FWD>>>(x, gXF);
    k_spec_kqv<<<1536, 512>>>(kqv_w1r, kqv_w1i, kqv_w2r, kqv_w2i);
    k_idft_kqv<<<1536, 256, SM_IDFTK>>>(x, kqv_skip);

    // attention over tokens
    k_zeroS<<<128, 256>>>();
    k_scores<<<dim3(256, 8), 256, SM_SCORES>>>();
    k_softmax<<<8, 64>>>();
    k_attnv<<<dim3(256, 8), 256>>>();

    // instance norm + gelu
    k_inorm<<<2048, 256>>>();

    // stage 2: end FNO block
    k_fwd_dft<<<2048, 256, SM_FWD>>>(gAtt, gXF);
    k_spec_end<<<128, 512>>>(end_w1r, end_w1i, end_w2r, end_w2i);
    k_idft_end<<<2048, 256>>>(out);
    k_endskip<<<dim3(128, 4, 8), 256>>>(end_skip, out);
}